// round 17
// baseline (speedup 1.0000x reference)
#include <cuda_runtime.h>
#include <cstdint>

// COO SpMM via fixed-capacity row buckets, D = 64.
// R17: pipeline overlap. Rows split into two halves; scatter(half1) runs
//      concurrently with spmm(half0) on a forked capture stream. Hot-loop
//      bodies are the frozen R10/R15 forms.

#define D_DIM    64
#define N_MAX    100000
#define E_MAX    3200000
#define CAP      128
#define OVF_CAP  8192

__device__ int  g_count[N_MAX];                  // memset per launch
__device__ int2 g_bucket[(size_t)N_MAX * CAP];   // {col, float bits of val}
__device__ int  g_ovf_count;                     // zero-init; self-reset
__device__ int4 g_ovf[OVF_CAP];                  // {row, col, valbits, 0}

// ---- Phase 1: bucket scatter for a row range ------------------------------------

__global__ void scatter_half(const int* __restrict__ idx,
                             const float* __restrict__ vals, int E,
                             int rowLo, int rowHi) {
    int e = blockIdx.x * blockDim.x + threadIdx.x;
    if (e >= E) return;
    int row = idx[e];
    if (row < rowLo || row >= rowHi) return;
    int col = idx[E + e];
    int vb  = __float_as_int(vals[e]);
    int pos = atomicAdd(&g_count[row], 1);
    if (pos < CAP) {
        g_bucket[(size_t)row * CAP + pos] = make_int2(col, vb);
    } else {
        int o = atomicAdd(&g_ovf_count, 1);
        if (o < OVF_CAP) g_ovf[o] = make_int4(row, col, vb, 0);
    }
}

// ---- Phase 2: one warp per row in [rowLo,rowHi) (exact R10 inner loop) ----------

__global__ void __launch_bounds__(256) spmm_half(const float* __restrict__ b,
                                                 float* __restrict__ out,
                                                 int rowLo, int rowHi) {
    int warp = (blockIdx.x * blockDim.x + threadIdx.x) >> 5;
    int lane = threadIdx.x & 31;
    int row  = rowLo + warp;
    if (row >= rowHi) return;

    int cnt = g_count[row];
    if (cnt > CAP) cnt = CAP;

    const int4* __restrict__ bkt4 =
        reinterpret_cast<const int4*>(g_bucket + (size_t)row * CAP);
    const float2* __restrict__ B = reinterpret_cast<const float2*>(b);
    float a0 = 0.f, a1 = 0.f;

    int pairs = cnt >> 1;
    #pragma unroll 2
    for (int i = 0; i < pairs; i++) {
        int4  p  = bkt4[i];
        float v0 = __int_as_float(p.y);
        float v1 = __int_as_float(p.w);
        float2 b0 = __ldg(&B[(long long)p.x * 32 + lane]);
        float2 b1 = __ldg(&B[(long long)p.z * 32 + lane]);
        a0 = fmaf(v0, b0.x, a0);
        a1 = fmaf(v0, b0.y, a1);
        a0 = fmaf(v1, b1.x, a0);
        a1 = fmaf(v1, b1.y, a1);
    }
    if (cnt & 1) {
        int2  p  = g_bucket[(size_t)row * CAP + (cnt - 1)];
        float v  = __int_as_float(p.y);
        float2 bv = __ldg(&B[(long long)p.x * 32 + lane]);
        a0 = fmaf(v, bv.x, a0);
        a1 = fmaf(v, bv.y, a1);
    }

    reinterpret_cast<float2*>(out)[(long long)row * 32 + lane] =
        make_float2(a0, a1);
}

// ---- Phase 3: overflow apply (1 block; normally instant exit) -------------------

__global__ void apply_overflow(const float* __restrict__ b,
                               float* __restrict__ out) {
    int novf = g_ovf_count;
    if (novf == 0) return;
    if (novf > OVF_CAP) novf = OVF_CAP;

    int t = threadIdx.x;
    for (int s = t; s < novf * 16; s += blockDim.x) {
        int  k = s >> 4;
        int  j = (s & 15) << 2;
        int4 ov = g_ovf[k];
        float v = __int_as_float(ov.z);
        const float4 bv =
            *reinterpret_cast<const float4*>(b + (long long)ov.y * D_DIM + j);
        float* dst = out + (long long)ov.x * D_DIM + j;
        asm volatile("red.global.add.v4.f32 [%0], {%1, %2, %3, %4};"
                     :: "l"(dst), "f"(bv.x * v), "f"(bv.y * v),
                        "f"(bv.z * v), "f"(bv.w * v)
                     : "memory");
    }
    __syncthreads();
    if (t == 0) g_ovf_count = 0;
}

// ---- Launch: fork-join pipeline over two row halves ------------------------------

extern "C" void kernel_launch(void* const* d_in, const int* in_sizes, int n_in,
                              void* d_out, int out_size) {
    const int*   idx  = (const int*)d_in[0];          // [2, E]
    const float* vals = (const float*)d_in[1];        // [E]
    const float* b    = (const float*)d_in[n_in - 1]; // [N, 64]
    float*       out  = (float*)d_out;

    int E = in_sizes[1];
    int N = out_size / D_DIM;
    if (E > E_MAX) E = E_MAX;
    if (N > N_MAX) N = N_MAX;
    int half = N / 2;

    // Static side-stream + events: created on the (uncaptured) correctness
    // call; only reused during graph capture. Host-side resources only.
    static cudaStream_t s_side = nullptr;
    static cudaEvent_t  ev_s0  = nullptr, ev_s1 = nullptr;
    if (s_side == nullptr) {
        cudaStreamCreateWithFlags(&s_side, cudaStreamNonBlocking);
        cudaEventCreateWithFlags(&ev_s0, cudaEventDisableTiming);
        cudaEventCreateWithFlags(&ev_s1, cudaEventDisableTiming);
    }

    void* count_ptr = nullptr;
    cudaGetSymbolAddress(&count_ptr, g_count);
    cudaMemsetAsync(count_ptr, 0, (size_t)N * sizeof(int));

    int eg = (E + 255) / 256;

    // S0: scatter rows [0, half)   (main stream)
    scatter_half<<<eg, 256>>>(idx, vals, E, 0, half);
    cudaEventRecord(ev_s0, 0);

    // S1: scatter rows [half, N)   (side stream, after S0)
    cudaStreamWaitEvent(s_side, ev_s0, 0);
    scatter_half<<<eg, 256, 0, s_side>>>(idx, vals, E, half, N);
    cudaEventRecord(ev_s1, s_side);

    // M0: spmm rows [0, half)      (main stream — overlaps S1)
    long long th0 = (long long)half * 32;
    spmm_half<<<(unsigned)((th0 + 255) / 256), 256>>>(b, out, 0, half);

    // join, then M1: spmm rows [half, N)
    cudaStreamWaitEvent(0, ev_s1, 0);
    long long th1 = (long long)(N - half) * 32;
    spmm_half<<<(unsigned)((th1 + 255) / 256), 256>>>(b, out, half, N);

    apply_overflow<<<1, 256>>>(b, out);
}